// round 13
// baseline (speedup 1.0000x reference)
#include <cuda_runtime.h>
#include <math.h>
#include <stdint.h>

// Problem shape (fixed by the dataset)
#define BB 4
#define TT 2048
#define HH 2048
#define MM (BB * TT)          // 8192 rows
#define NTOT (MM * HH)        // 16,777,216 elements per activation tensor
#define WTOT (HH * HH)        // 4,194,304 elements per weight

// ---------------- static scratch (__device__ globals) -----------------------
// tf32-pre-rounded f32 hi/lo splits
__device__ float gKhi[NTOT], gKlo[NTOT];
__device__ float gVhi[NTOT], gVlo[NTOT];
__device__ float gRhi[NTOT], gRlo[NTOT];   // reused for gate splits after GEMM3
__device__ float gWkhi[WTOT], gWklo[WTOT];
__device__ float gWvhi[WTOT], gWvlo[WTOT];
__device__ float gWrhi[WTOT], gWrlo[WTOT];
__device__ float gWohi[WTOT], gWolo[WTOT];
__device__ float gK[NTOT];
__device__ float gV[NTOT];
__device__ float gR[NTOT];
__device__ float gWKV[NTOT];

// ---------------------------------------------------------------------------
// helpers
// ---------------------------------------------------------------------------
__device__ __forceinline__ uint32_t smem_u32(const void* p) {
    return (uint32_t)__cvta_generic_to_shared(p);
}
__device__ __forceinline__ void cp16(uint32_t dst, const void* src) {
    asm volatile("cp.async.ca.shared.global [%0], [%1], 16;" :: "r"(dst), "l"(src));
}
__device__ __forceinline__ void split_tf32(float x, float& hi, float& lo) {
    uint32_t h;
    asm("cvt.rna.tf32.f32 %0, %1;" : "=r"(h) : "f"(x));
    hi = __uint_as_float(h);
    uint32_t l;
    float r = x - hi;
    asm("cvt.rna.tf32.f32 %0, %1;" : "=r"(l) : "f"(r));
    lo = __uint_as_float(l);
}

#define MMA_TF32(c, a0, a1, a2, a3, b0, b1)                                   \
    asm volatile(                                                             \
        "mma.sync.aligned.m16n8k8.row.col.f32.tf32.tf32.f32 "                 \
        "{%0,%1,%2,%3},{%4,%5,%6,%7},{%8,%9},{%0,%1,%2,%3};"                  \
        : "+f"(c[0]), "+f"(c[1]), "+f"(c[2]), "+f"(c[3])                      \
        : "r"(a0), "r"(a1), "r"(a2), "r"(a3), "r"(b0), "r"(b1))

// ---------------------------------------------------------------------------
// 1) time-shift + mix + tf32 hi/lo split (f32 storage). 2 elements/thread.
// ---------------------------------------------------------------------------
__global__ __launch_bounds__(256) void mix_split_kernel(
    const float* __restrict__ hidden,
    const float* __restrict__ mixk,
    const float* __restrict__ mixv,
    const float* __restrict__ mixr,
    float* __restrict__ Khi, float* __restrict__ Klo,
    float* __restrict__ Vhi, float* __restrict__ Vlo,
    float* __restrict__ Rhi, float* __restrict__ Rlo)
{
    size_t gid2 = (size_t)blockIdx.x * blockDim.x + threadIdx.x;
    if (gid2 >= (size_t)NTOT / 2) return;
    size_t e = gid2 * 2;
    int h = (int)(e % HH);
    int t = (int)((e / HH) % TT);

    float2 hd = *reinterpret_cast<const float2*>(hidden + e);
    float2 sh = make_float2(0.0f, 0.0f);
    if (t > 0) sh = *reinterpret_cast<const float2*>(hidden + e - HH);

    float2 mk = *reinterpret_cast<const float2*>(mixk + h);
    float2 mv = *reinterpret_cast<const float2*>(mixv + h);
    float2 mr = *reinterpret_cast<const float2*>(mixr + h);

#define EMIT(HI, LO, MX)                                                      \
    {                                                                         \
        float v0 = hd.x * MX.x + sh.x * (1.0f - MX.x);                        \
        float v1 = hd.y * MX.y + sh.y * (1.0f - MX.y);                        \
        float h0, l0, h1, l1;                                                 \
        split_tf32(v0, h0, l0);                                               \
        split_tf32(v1, h1, l1);                                               \
        *reinterpret_cast<float2*>(HI + e) = make_float2(h0, h1);             \
        *reinterpret_cast<float2*>(LO + e) = make_float2(l0, l1);             \
    }
    EMIT(Khi, Klo, mk)
    EMIT(Vhi, Vlo, mv)
    EMIT(Rhi, Rlo, mr)
#undef EMIT
}

// ---------------------------------------------------------------------------
// 1b) weight split (elementwise, NO transpose): W[k][n] -> Whi/Wlo[k][n]
// ---------------------------------------------------------------------------
__global__ __launch_bounds__(256) void wsplit_kernel(
    const float* __restrict__ W,
    float* __restrict__ Whi,
    float* __restrict__ Wlo)
{
    size_t gid2 = (size_t)blockIdx.x * blockDim.x + threadIdx.x;
    if (gid2 >= (size_t)WTOT / 2) return;
    size_t e = gid2 * 2;
    float2 w = *reinterpret_cast<const float2*>(W + e);
    float h0, l0, h1, l1;
    split_tf32(w.x, h0, l0);
    split_tf32(w.y, h1, l1);
    *reinterpret_cast<float2*>(Whi + e) = make_float2(h0, h1);
    *reinterpret_cast<float2*>(Wlo + e) = make_float2(l0, l1);
}

// ---------------------------------------------------------------------------
// 2) TF32 tensor-core GEMM with precomputed 3x split.
//    Identical structure/indexing to the PROVEN round-3 kernel; the only
//    change: operands come pre-split (hi/lo) so the inner loop has zero
//    cvt/sub ALU. C[M,N] = A[M,K] * B[K,N], row-major.
//    CTA 128x128, BK=16, 256 threads, warp tile 64x32, mma.m16n8k8.
// ---------------------------------------------------------------------------
#define BM 128
#define BN 128
#define BKg 16
#define AST 20      // A smem row stride (floats)
#define BST 136     // B smem row stride (floats)
#define ASZ (BM * AST)      // 2560 floats per A buffer
#define BSZ (BKg * BST)     // 2176 floats per B buffer
#define GEMM_SMEM ((4 * ASZ + 4 * BSZ) * 4)   // 75776 bytes

__global__ __launch_bounds__(256, 1) void gemm_tf32pre(
    const float* __restrict__ Ahi,
    const float* __restrict__ Alo,
    const float* __restrict__ Bhi,
    const float* __restrict__ Blo,
    float* __restrict__ C,
    int M, int N, int K)
{
    extern __shared__ float smf[];
    float* AsH = smf;                  // [2][BM][AST]
    float* AsL = smf + 2 * ASZ;        // [2][BM][AST]
    float* BsH = smf + 4 * ASZ;        // [2][BKg][BST]
    float* BsL = smf + 4 * ASZ + 2 * BSZ;

    const int bx = blockIdx.x;     // N tile
    const int by = blockIdx.y;     // M tile
    const int tid = threadIdx.x;
    const int wid = tid >> 5;
    const int lane = tid & 31;
    const int g = lane >> 2;         // 0..7
    const int tig = lane & 3;        // 0..3
    const int wm = (wid >> 2) * 64;  // 0 or 64
    const int wn = (wid & 3) * 32;   // 0,32,64,96

    const float* AbH = Ahi + (size_t)by * BM * K;
    const float* AbL = Alo + (size_t)by * BM * K;
    const float* BbH = Bhi + (size_t)bx * BN;
    const float* BbL = Blo + (size_t)bx * BN;

    // global->smem load indices (identical to round-3 kernel)
    const int arow = tid >> 2;          // 0..63
    const int ac4  = (tid & 3) * 4;     // 0,4,8,12
    const int brow = tid >> 5;          // 0..7
    const int bc4  = (tid & 31) * 4;    // 0..124

    float acc[4][4][4];
#pragma unroll
    for (int i = 0; i < 4; i++)
#pragma unroll
        for (int j = 0; j < 4; j++)
#pragma unroll
            for (int e = 0; e < 4; e++) acc[i][j][e] = 0.0f;

#define LOAD_TILES(buf, k0)                                                    \
    {                                                                          \
        uint32_t a0 = smem_u32(AsH + (buf) * ASZ + arow * AST + ac4);          \
        uint32_t a1 = smem_u32(AsH + (buf) * ASZ + (arow + 64) * AST + ac4);   \
        uint32_t l0 = smem_u32(AsL + (buf) * ASZ + arow * AST + ac4);          \
        uint32_t l1 = smem_u32(AsL + (buf) * ASZ + (arow + 64) * AST + ac4);   \
        cp16(a0, AbH + (size_t)arow * K + (k0) + ac4);                         \
        cp16(a1, AbH + (size_t)(arow + 64) * K + (k0) + ac4);                  \
        cp16(l0, AbL + (size_t)arow * K + (k0) + ac4);                         \
        cp16(l1, AbL + (size_t)(arow + 64) * K + (k0) + ac4);                  \
        uint32_t b0 = smem_u32(BsH + (buf) * BSZ + brow * BST + bc4);          \
        uint32_t b1 = smem_u32(BsH + (buf) * BSZ + (brow + 8) * BST + bc4);    \
        uint32_t m0 = smem_u32(BsL + (buf) * BSZ + brow * BST + bc4);          \
        uint32_t m1 = smem_u32(BsL + (buf) * BSZ + (brow + 8) * BST + bc4);    \
        cp16(b0, BbH + (size_t)((k0) + brow) * N + bc4);                       \
        cp16(b1, BbH + (size_t)((k0) + brow + 8) * N + bc4);                   \
        cp16(m0, BbL + (size_t)((k0) + brow) * N + bc4);                       \
        cp16(m1, BbL + (size_t)((k0) + brow + 8) * N + bc4);                   \
    }

    LOAD_TILES(0, 0)
    asm volatile("cp.async.commit_group;");

    const int nk = K / BKg;   // 128

    for (int i = 0; i < nk; i++) {
        const int cur = i & 1;
        if (i + 1 < nk) {
            LOAD_TILES(cur ^ 1, (i + 1) * BKg)
        }
        asm volatile("cp.async.commit_group;");
        asm volatile("cp.async.wait_group 1;");
        __syncthreads();

        const float* pAH = AsH + cur * ASZ;
        const float* pAL = AsL + cur * ASZ;
        const float* pBH = BsH + cur * BSZ;
        const float* pBL = BsL + cur * BSZ;

#pragma unroll
        for (int ks = 0; ks < BKg; ks += 8) {
            uint32_t aH[4][4], aL[4][4], bH[4][2], bL[4][2];
#pragma unroll
            for (int mt = 0; mt < 4; mt++) {
                const int r0 = wm + mt * 16 + g;
                const int o00 = r0 * AST + ks + tig;
                const int o10 = (r0 + 8) * AST + ks + tig;
                aH[mt][0] = *reinterpret_cast<const uint32_t*>(pAH + o00);
                aH[mt][1] = *reinterpret_cast<const uint32_t*>(pAH + o10);
                aH[mt][2] = *reinterpret_cast<const uint32_t*>(pAH + o00 + 4);
                aH[mt][3] = *reinterpret_cast<const uint32_t*>(pAH + o10 + 4);
                aL[mt][0] = *reinterpret_cast<const uint32_t*>(pAL + o00);
                aL[mt][1] = *reinterpret_cast<const uint32_t*>(pAL + o10);
                aL[mt][2] = *reinterpret_cast<const uint32_t*>(pAL + o00 + 4);
                aL[mt][3] = *reinterpret_cast<const uint32_t*>(pAL + o10 + 4);
            }
#pragma unroll
            for (int nt = 0; nt < 4; nt++) {
                const int col = wn + nt * 8 + g;
                const int o0 = (ks + tig) * BST + col;
                const int o1 = (ks + tig + 4) * BST + col;
                bH[nt][0] = *reinterpret_cast<const uint32_t*>(pBH + o0);
                bH[nt][1] = *reinterpret_cast<const uint32_t*>(pBH + o1);
                bL[nt][0] = *reinterpret_cast<const uint32_t*>(pBL + o0);
                bL[nt][1] = *reinterpret_cast<const uint32_t*>(pBL + o1);
            }
#pragma unroll
            for (int mt = 0; mt < 4; mt++) {
#pragma unroll
                for (int nt = 0; nt < 4; nt++) {
                    MMA_TF32(acc[mt][nt], aH[mt][0], aH[mt][1], aH[mt][2], aH[mt][3],
                             bH[nt][0], bH[nt][1]);
                    MMA_TF32(acc[mt][nt], aL[mt][0], aL[mt][1], aL[mt][2], aL[mt][3],
                             bH[nt][0], bH[nt][1]);
                    MMA_TF32(acc[mt][nt], aH[mt][0], aH[mt][1], aH[mt][2], aH[mt][3],
                             bL[nt][0], bL[nt][1]);
                }
            }
        }
        __syncthreads();
    }
#undef LOAD_TILES

    // epilogue (identical to round-3 kernel)
#pragma unroll
    for (int mt = 0; mt < 4; mt++) {
#pragma unroll
        for (int nt = 0; nt < 4; nt++) {
            const size_t row0 = (size_t)by * BM + wm + mt * 16 + g;
            const size_t col  = (size_t)bx * BN + wn + nt * 8 + 2 * tig;
            *reinterpret_cast<float2*>(C + row0 * N + col) =
                make_float2(acc[mt][nt][0], acc[mt][nt][1]);
            *reinterpret_cast<float2*>(C + (row0 + 8) * N + col) =
                make_float2(acc[mt][nt][2], acc[mt][nt][3]);
        }
    }
}

// ---------------------------------------------------------------------------
// 3) WKV recurrence. One thread per (b, d) channel, sequential over T.
// ---------------------------------------------------------------------------
__global__ __launch_bounds__(128) void wkv_kernel(
    const float* __restrict__ time_decay,
    const float* __restrict__ time_first,
    const float* __restrict__ k,
    const float* __restrict__ v,
    float* __restrict__ out)
{
    int gid = blockIdx.x * blockDim.x + threadIdx.x;
    if (gid >= BB * HH) return;
    int d = gid % HH;
    int b = gid / HH;

    const float td = -expf(time_decay[d]);
    const float tf = time_first[d];

    float num = 0.0f, den = 0.0f, mx = -1e38f;

    const size_t base = (size_t)b * TT * HH + d;
    const float* kp = k + base;
    const float* vp = v + base;
    float* op = out + base;

    for (int t = 0; t < TT; t++) {
        const size_t off = (size_t)t * HH;
        float kt = kp[off];
        float vt = vp[off];

        float ktf = kt + tf;
        float mfo = fmaxf(mx, ktf);
        float e1 = expf(mx - mfo);
        float e2 = expf(ktf - mfo);
        op[off] = (e1 * num + e2 * vt) / (e1 * den + e2);

        float mxd = mx + td;
        float mfs = fmaxf(mxd, kt);
        float e1s = expf(mxd - mfs);
        float e2s = expf(kt - mfs);
        num = e1s * num + e2s * vt;
        den = e1s * den + e2s;
        mx = mfs;
    }
}

// ---------------------------------------------------------------------------
// 4) gate + tf32 split: g = sigmoid(r) * wkv -> Ghi/Glo (f32)
// ---------------------------------------------------------------------------
__global__ __launch_bounds__(256) void gate_split_kernel(
    const float* __restrict__ rlin,
    const float* __restrict__ wkv,
    float* __restrict__ Ghi,
    float* __restrict__ Glo)
{
    size_t gid2 = (size_t)blockIdx.x * blockDim.x + threadIdx.x;
    if (gid2 >= (size_t)NTOT / 2) return;
    size_t e = gid2 * 2;
    float2 r = *reinterpret_cast<const float2*>(rlin + e);
    float2 w = *reinterpret_cast<const float2*>(wkv + e);
    float g0 = w.x / (1.0f + expf(-r.x));
    float g1 = w.y / (1.0f + expf(-r.y));
    float h0, l0, h1, l1;
    split_tf32(g0, h0, l0);
    split_tf32(g1, h1, l1);
    *reinterpret_cast<float2*>(Ghi + e) = make_float2(h0, h1);
    *reinterpret_cast<float2*>(Glo + e) = make_float2(l0, l1);
}

// ---------------------------------------------------------------------------
// launch
// ---------------------------------------------------------------------------
extern "C" void kernel_launch(void* const* d_in, const int* in_sizes, int n_in,
                              void* d_out, int out_size)
{
    const float* hidden = (const float*)d_in[0];
    const float* time_decay = (const float*)d_in[1];
    const float* time_first = (const float*)d_in[2];
    const float* mixk = (const float*)d_in[3];
    const float* mixv = (const float*)d_in[4];
    const float* mixr = (const float*)d_in[5];
    const float* Wk = (const float*)d_in[6];
    const float* Wv = (const float*)d_in[7];
    const float* Wr = (const float*)d_in[8];
    const float* Wo = (const float*)d_in[9];
    float* out = (float*)d_out;

    cudaFuncSetAttribute(gemm_tf32pre,
                         cudaFuncAttributeMaxDynamicSharedMemorySize, GEMM_SMEM);

#define SYM(p, s) float* p; cudaGetSymbolAddress((void**)&p, s)
    SYM(pKhi, gKhi); SYM(pKlo, gKlo);
    SYM(pVhi, gVhi); SYM(pVlo, gVlo);
    SYM(pRhi, gRhi); SYM(pRlo, gRlo);
    SYM(pWkhi, gWkhi); SYM(pWklo, gWklo);
    SYM(pWvhi, gWvhi); SYM(pWvlo, gWvlo);
    SYM(pWrhi, gWrhi); SYM(pWrlo, gWrlo);
    SYM(pWohi, gWohi); SYM(pWolo, gWolo);
    SYM(pK, gK); SYM(pV, gV); SYM(pR, gR); SYM(pWKV, gWKV);
#undef SYM

    // 1) mix + split
    {
        int blocks = (NTOT / 2 + 255) / 256;
        mix_split_kernel<<<blocks, 256>>>(hidden, mixk, mixv, mixr,
                                          pKhi, pKlo, pVhi, pVlo, pRhi, pRlo);
    }

    // 1b) weight splits (elementwise)
    {
        int blocks = (WTOT / 2 + 255) / 256;
        wsplit_kernel<<<blocks, 256>>>(Wk, pWkhi, pWklo);
        wsplit_kernel<<<blocks, 256>>>(Wv, pWvhi, pWvlo);
        wsplit_kernel<<<blocks, 256>>>(Wr, pWrhi, pWrlo);
        wsplit_kernel<<<blocks, 256>>>(Wo, pWohi, pWolo);
    }

    // 2) three input GEMMs
    dim3 ggrid(HH / BN, MM / BM);   // (16, 64)
    gemm_tf32pre<<<ggrid, 256, GEMM_SMEM>>>(pKhi, pKlo, pWkhi, pWklo, pK, MM, HH, HH);
    gemm_tf32pre<<<ggrid, 256, GEMM_SMEM>>>(pVhi, pVlo, pWvhi, pWvlo, pV, MM, HH, HH);
    gemm_tf32pre<<<ggrid, 256, GEMM_SMEM>>>(pRhi, pRlo, pWrhi, pWrlo, pR, MM, HH, HH);

    // 3) WKV recurrence
    wkv_kernel<<<(BB * HH) / 128, 128>>>(time_decay, time_first, pK, pV, pWKV);

    // 4) gate + split (reuse gRhi/gRlo — already consumed by GEMM3)
    {
        int blocks = (NTOT / 2 + 255) / 256;
        gate_split_kernel<<<blocks, 256>>>(pR, pWKV, pRhi, pRlo);
    }

    // 5) output GEMM -> d_out
    gemm_tf32pre<<<ggrid, 256, GEMM_SMEM>>>(pRhi, pRlo, pWohi, pWolo, out, MM, HH, HH);
}